// round 16
// baseline (speedup 1.0000x reference)
#include <cuda_runtime.h>
#include <cuda_fp16.h>
#include <cstdint>

#define NTOK 16384
#define DM   1024
#define NH   16
#define HD   64
#define KD   1024

// ---------------- scratch ----------------
__device__ __half g_hq [(size_t)NTOK * DM];
__device__ __half g_hk [(size_t)NTOK * DM];
__device__ __half g_hv [(size_t)NTOK * DM];
__device__ __half g_hWq[(size_t)DM * DM];
__device__ __half g_hWk[(size_t)DM * DM];
__device__ __half g_hWv[(size_t)DM * DM];
__device__ __half g_hWo[(size_t)DM * DM];
__device__ __half g_qh [(size_t)NTOK * DM];
__device__ __half g_kh [(size_t)NTOK * DM];
__device__ __half g_vh [(size_t)NTOK * DM];
__device__ __half g_att[(size_t)NTOK * DM];

__device__ __forceinline__ uint32_t smem_u32(const void* p) {
    uint32_t a;
    asm("{ .reg .u64 t; cvta.to.shared.u64 t, %1; cvt.u32.u64 %0, t; }" : "=r"(a) : "l"(p));
    return a;
}

// ---------------------------------------------------------------------------
// GEMM (frozen — at the legacy-HMMA hardware rate):
// BM=128 BN=128 BK=64, 128 thr, 4 warps (2x2), warp tile 64x64,
// NST=3 cp.async pipeline, 96KB smem, 2 CTAs/SM.
// ---------------------------------------------------------------------------
#define BM 128
#define BN 128
#define BK 64
#define NKT (KD / BK)            // 16
#define NST 3
#define ASTG 16384
#define BSTG 16384
#define BOFF (NST * ASTG)
#define GEMM_SMEM (NST * (ASTG + BSTG))   // 98304
#define GTHR 128

#define LDSM_X4(r0, r1, r2, r3, addr)                                           \
    asm volatile("ldmatrix.sync.aligned.m8n8.x4.shared.b16 {%0,%1,%2,%3}, [%4];" \
                 : "=r"(r0), "=r"(r1), "=r"(r2), "=r"(r3) : "r"(addr))

#define MMA_F16(acc, a, b0, b1)                                                 \
    asm volatile("mma.sync.aligned.m16n8k16.row.col.f32.f16.f16.f32 "           \
                 "{%0,%1,%2,%3}, {%4,%5,%6,%7}, {%8,%9}, {%0,%1,%2,%3};\n"      \
                 : "+f"((acc)[0]), "+f"((acc)[1]), "+f"((acc)[2]), "+f"((acc)[3]) \
                 : "r"((a)[0]), "r"((a)[1]), "r"((a)[2]), "r"((a)[3]),          \
                   "r"(b0), "r"(b1))

#define CP_ASYNC16(dst, src) \
    asm volatile("cp.async.cg.shared.global [%0], [%1], 16;" :: "r"(dst), "l"(src))
#define CP_COMMIT() asm volatile("cp.async.commit_group;")
#define CP_WAIT1()  asm volatile("cp.async.wait_group 1;")

template <typename OutT, int NZ>
__global__ __launch_bounds__(GTHR, 2)
void gemm_h(const __half* __restrict__ A0, const __half* __restrict__ W0,
            const float* __restrict__ b0_, OutT* __restrict__ C0,
            const __half* __restrict__ A1, const __half* __restrict__ W1,
            const float* __restrict__ b1_, OutT* __restrict__ C1,
            const __half* __restrict__ A2, const __half* __restrict__ W2,
            const float* __restrict__ b2_, OutT* __restrict__ C2)
{
    const __half* A;   const __half* W;
    const float*  bias; OutT* C;
    if (NZ == 1 || blockIdx.z == 0) { A = A0; W = W0; bias = b0_; C = C0; }
    else if (blockIdx.z == 1)       { A = A1; W = W1; bias = b1_; C = C1; }
    else                            { A = A2; W = W2; bias = b2_; C = C2; }

    extern __shared__ char smem[];
    const uint32_t sb = smem_u32(smem);

    const int t    = threadIdx.x;
    const int warp = t >> 5;
    const int lane = t & 31;
    const int wm   = warp >> 1;
    const int wn   = warp & 1;
    const int m0   = blockIdx.y * BM;
    const int n0   = blockIdx.x * BN;

    auto stage = [&](int kt) {
        const int s = (kt % NST);
        const uint32_t sa = sb + s * ASTG;
        const uint32_t sw = sb + BOFF + s * BSTG;
        #pragma unroll
        for (int i = 0; i < 8; i++) {
            int id  = t + i * GTHR;
            int row = id >> 3, c16 = id & 7;
            const __half* src = A + (size_t)(m0 + row) * KD + kt * BK + c16 * 8;
            CP_ASYNC16(sa + row * 128 + ((c16 ^ (row & 7)) << 4), src);
        }
        #pragma unroll
        for (int i = 0; i < 8; i++) {
            int id  = t + i * GTHR;
            int row = id >> 3, c16 = id & 7;
            const __half* src = W + (size_t)(n0 + row) * KD + kt * BK + c16 * 8;
            CP_ASYNC16(sw + row * 128 + ((c16 ^ (row & 7)) << 4), src);
        }
    };

    float acc[4][8][4];
    #pragma unroll
    for (int mi = 0; mi < 4; mi++)
        #pragma unroll
        for (int ni = 0; ni < 8; ni++)
            #pragma unroll
            for (int r = 0; r < 4; r++) acc[mi][ni][r] = 0.f;

    const int tl   = lane >> 3;
    const int tr   = lane & 7;
    const int rsel = (tl & 1) * 8;
    const int khh  = tl >> 1;

    uint32_t aRow[4], bRow[4];
    #pragma unroll
    for (int mi = 0; mi < 4; mi++) aRow[mi] = (wm * 64 + mi * 16 + rsel + tr) * 128;
    #pragma unroll
    for (int nj = 0; nj < 4; nj++) bRow[nj] = (wn * 64 + nj * 16 + rsel + tr) * 128;

    auto compute = [&](int s) {
        const uint32_t aB = sb + s * ASTG;
        const uint32_t bB = sb + BOFF + s * BSTG;
        #pragma unroll
        for (int ks = 0; ks < 4; ks++) {
            const uint32_t kcx = (uint32_t)(((ks * 2 + khh) ^ tr) << 4);
            uint32_t a[4][4], bf[4][4];
            #pragma unroll
            for (int mi = 0; mi < 4; mi++)
                LDSM_X4(a[mi][0], a[mi][1], a[mi][2], a[mi][3], aB + aRow[mi] + kcx);
            #pragma unroll
            for (int nj = 0; nj < 4; nj++)
                LDSM_X4(bf[nj][0], bf[nj][1], bf[nj][2], bf[nj][3], bB + bRow[nj] + kcx);
            #pragma unroll
            for (int mi = 0; mi < 4; mi++)
                #pragma unroll
                for (int n8 = 0; n8 < 8; n8++) {
                    const int nj = n8 >> 1, hi = n8 & 1;
                    MMA_F16(acc[mi][n8], a[mi], bf[nj][hi], bf[nj][hi + 2]);
                }
        }
    };

    stage(0); CP_COMMIT();
    stage(1); CP_COMMIT();

    for (int kt = 0; kt < NKT; kt++) {
        CP_WAIT1();
        __syncthreads();
        if (kt + 2 < NKT) stage(kt + 2);
        CP_COMMIT();
        compute(kt % NST);
    }

    const int gq = lane >> 2, tg = lane & 3;
    #pragma unroll
    for (int mi = 0; mi < 4; mi++) {
        const int r = m0 + wm * 64 + mi * 16 + gq;
        #pragma unroll
        for (int ni = 0; ni < 8; ni++) {
            const int cc = n0 + wn * 64 + ni * 8 + tg * 2;
            const float bb0 = __ldg(bias + cc);
            const float bb1 = __ldg(bias + cc + 1);
            if constexpr (sizeof(OutT) == 2) {
                *(__half2*)((__half*)C + (size_t)r * DM + cc) =
                    __floats2half2_rn(acc[mi][ni][0] + bb0, acc[mi][ni][1] + bb1);
                *(__half2*)((__half*)C + (size_t)(r + 8) * DM + cc) =
                    __floats2half2_rn(acc[mi][ni][2] + bb0, acc[mi][ni][3] + bb1);
            } else {
                *(float2*)((float*)C + (size_t)r * DM + cc) =
                    make_float2(acc[mi][ni][0] + bb0, acc[mi][ni][1] + bb1);
                *(float2*)((float*)C + (size_t)(r + 8) * DM + cc) =
                    make_float2(acc[mi][ni][2] + bb0, acc[mi][ni][3] + bb1);
            }
        }
    }
}

// ---------------- fused fp32 -> fp16 conversion (single launch) -------------
__global__ __launch_bounds__(256)
void cvt_all(const float4* __restrict__ q,  uint2* __restrict__ hq,
             const float4* __restrict__ k,  uint2* __restrict__ hk,
             const float4* __restrict__ v,  uint2* __restrict__ hv,
             const float4* __restrict__ w0, uint2* __restrict__ hw0,
             const float4* __restrict__ w1, uint2* __restrict__ hw1,
             const float4* __restrict__ w2, uint2* __restrict__ hw2,
             const float4* __restrict__ w3, uint2* __restrict__ hw3)
{
    const int b = blockIdx.x;
    const float4* in;
    uint2* out;
    int lb;
    if (b < 12288) {
        int ts = b >> 12;
        lb = b & 4095;
        in  = (ts == 0) ? q  : (ts == 1) ? k  : v;
        out = (ts == 0) ? hq : (ts == 1) ? hk : hv;
    } else {
        int w = b - 12288;
        int ts = w >> 8;
        lb = w & 255;
        in  = (ts == 0) ? w0  : (ts == 1) ? w1  : (ts == 2) ? w2  : w3;
        out = (ts == 0) ? hw0 : (ts == 1) ? hw1 : (ts == 2) ? hw2 : hw3;
    }
    int base = lb * 1024 + threadIdx.x;
    float4 vv[4];
    #pragma unroll
    for (int j = 0; j < 4; j++) vv[j] = in[base + j * 256];
    #pragma unroll
    for (int j = 0; j < 4; j++) {
        __half2 h0 = __floats2half2_rn(vv[j].x, vv[j].y);
        __half2 h1 = __floats2half2_rn(vv[j].z, vv[j].w);
        out[base + j * 256] = make_uint2(*(uint32_t*)&h0, *(uint32_t*)&h1);
    }
}

// ---------------- per-token head-mixing attention (v5) ----------------------
// TPB=2; q/k fp16 smem + hfma2 scores; V pre-converted to fp32 smem for AV.
#define QROW 9    // uint4 per smem row (8 data + 1 pad)
#define VROW 68   // floats per V smem row (64 data + 4 pad)

__global__ __launch_bounds__(256)
void head_attn(const __half* __restrict__ qh, const __half* __restrict__ kh,
               const __half* __restrict__ vh, __half* __restrict__ out)
{
    __shared__ uint4 qsh[2][NH * QROW];
    __shared__ uint4 ksh[2][NH * QROW];
    __shared__ float vsf[2][NH * VROW];
    __shared__ float sc[2][NH][NH + 1];

    const int tok0 = blockIdx.x * 2;
    const int t    = threadIdx.x;

    {   // load q/k (fp16) and v (widen to fp32 once — exact)
        int row = t >> 3;                  // 0..31
        int ti  = row >> 4;
        int r   = row & 15;
        int c   = t & 7;                   // uint4 chunk (8 halfs)
        const size_t base = (size_t)(tok0 + ti) * DM + r * HD;
        qsh[ti][r * QROW + c] = *((const uint4*)(qh + base) + c);
        ksh[ti][r * QROW + c] = *((const uint4*)(kh + base) + c);
        uint4 va = *((const uint4*)(vh + base) + c);
        float2 f0 = __half22float2(*(__half2*)&va.x);
        float2 f1 = __half22float2(*(__half2*)&va.y);
        float2 f2 = __half22float2(*(__half2*)&va.z);
        float2 f3 = __half22float2(*(__half2*)&va.w);
        float* vd = &vsf[ti][r * VROW + c * 8];
        *(float4*)(vd)     = make_float4(f0.x, f0.y, f1.x, f1.y);
        *(float4*)(vd + 4) = make_float4(f2.x, f2.y, f3.x, f3.y);
    }
    __syncthreads();

    {   // scores: hfma2 chains (8 parallel half2 chains of 8)
        const int h = t >> 4, g = t & 15;
        #pragma unroll
        for (int ti = 0; ti < 2; ti++) {
            const uint4* qr = &qsh[ti][h * QROW];
            const uint4* kr = &ksh[ti][g * QROW];
            uint4 qa = qr[0], ka = kr[0];
            __half2 a0 = __hmul2(*(__half2*)&qa.x, *(__half2*)&ka.x);
            __half2 a1 = __hmul2(*(__half2*)&qa.y, *(__half2*)&ka.y);
            __half2 a2 = __hmul2(*(__half2*)&qa.z, *(__half2*)&ka.z);
            __half2 a3 = __hmul2(*(__half2*)&qa.w, *(__half2*)&ka.w);
            #pragma unroll
            for (int c = 1; c < 8; c++) {
                qa = qr[c]; ka = kr[c];
                a0 = __hfma2(*(__half2*)&qa.x, *(__half2*)&ka.x, a0);
                a1 = __hfma2(*(__half2*)&qa.y, *(__half2*)&ka.y, a1);
                a2 = __hfma2(*(__half2*)&qa.z, *(__half2*)&ka.z, a2);
                a3 = __hfma2(*(__half2*)&qa.w, *(__half2*)&ka.w, a3);
            }
            float2 f0 = __half22float2(a0);
            float2 f1 = __half22float2(a1);
            float2 f2 = __half22float2(a2);
            float2 f3 = __half22float2(a3);
            float s = (f0.x + f0.y) + (f1.x + f1.y)
                    + (f2.x + f2.y) + (f3.x + f3.y);
            sc[ti][h][g] = s * 0.125f;
        }
    }
    __syncthreads();

    if (t < 32) {   // softmax
        int ti = t >> 4, r = t & 15;
        float m = sc[ti][r][0];
        #pragma unroll
        for (int g = 1; g < NH; g++) m = fmaxf(m, sc[ti][r][g]);
        float e[NH], sum = 0.f;
        #pragma unroll
        for (int g = 0; g < NH; g++) { e[g] = __expf(sc[ti][r][g] - m); sum += e[g]; }
        float inv = 1.f / sum;
        #pragma unroll
        for (int g = 0; g < NH; g++) sc[ti][r][g] = e[g] * inv;
    }
    __syncthreads();

    {   // AV: pure fp32 FFMA on pre-converted V
        const int h  = t >> 4;
        const int c2 = t & 15;             // float4 chunk
        #pragma unroll
        for (int ti = 0; ti < 2; ti++) {
            float4 acc = make_float4(0.f, 0.f, 0.f, 0.f);
            #pragma unroll
            for (int g = 0; g < NH; g++) {
                float w = sc[ti][h][g];
                float4 vv = *(const float4*)&vsf[ti][g * VROW + c2 * 4];
                acc.x += w * vv.x; acc.y += w * vv.y;
                acc.z += w * vv.z; acc.w += w * vv.w;
            }
            __half2 h0 = __floats2half2_rn(acc.x, acc.y);
            __half2 h1 = __floats2half2_rn(acc.z, acc.w);
            *(uint2*)(out + (size_t)(tok0 + ti) * DM + h * HD + c2 * 4) =
                make_uint2(*(uint32_t*)&h0, *(uint32_t*)&h1);
        }
    }
}

// ---------------------------------------------------------------------------
extern "C" void kernel_launch(void* const* d_in, const int* in_sizes, int n_in,
                              void* d_out, int out_size)
{
    const float* q  = (const float*)d_in[0];
    const float* k  = (const float*)d_in[1];
    const float* v  = (const float*)d_in[2];
    const float* Wq = (const float*)d_in[3];
    const float* bq = (const float*)d_in[4];
    const float* Wk = (const float*)d_in[5];
    const float* bk = (const float*)d_in[6];
    const float* Wv = (const float*)d_in[7];
    const float* bv = (const float*)d_in[8];
    const float* Wo = (const float*)d_in[9];
    const float* bo = (const float*)d_in[10];
    float* out = (float*)d_out;

    __half *hq, *hk, *hv, *hWq, *hWk, *hWv, *hWo, *qh, *kh, *vh, *att;
    cudaGetSymbolAddress((void**)&hq,  g_hq);
    cudaGetSymbolAddress((void**)&hk,  g_hk);
    cudaGetSymbolAddress((void**)&hv,  g_hv);
    cudaGetSymbolAddress((void**)&hWq, g_hWq);
    cudaGetSymbolAddress((void**)&hWk, g_hWk);
    cudaGetSymbolAddress((void**)&hWv, g_hWv);
    cudaGetSymbolAddress((void**)&hWo, g_hWo);
    cudaGetSymbolAddress((void**)&qh,  g_qh);
    cudaGetSymbolAddress((void**)&kh,  g_kh);
    cudaGetSymbolAddress((void**)&vh,  g_vh);
    cudaGetSymbolAddress((void**)&att, g_att);

    cudaFuncSetAttribute((const void*)gemm_h<__half, 3>,
                         cudaFuncAttributeMaxDynamicSharedMemorySize, GEMM_SMEM);
    cudaFuncSetAttribute((const void*)gemm_h<float, 1>,
                         cudaFuncAttributeMaxDynamicSharedMemorySize, GEMM_SMEM);

    cvt_all<<<13312, 256>>>((const float4*)q,  (uint2*)hq,
                            (const float4*)k,  (uint2*)hk,
                            (const float4*)v,  (uint2*)hv,
                            (const float4*)Wq, (uint2*)hWq,
                            (const float4*)Wk, (uint2*)hWk,
                            (const float4*)Wv, (uint2*)hWv,
                            (const float4*)Wo, (uint2*)hWo);

    dim3 gp(DM / BN, NTOK / BM, 3);   // (8, 128, 3)
    gemm_h<__half, 3><<<gp, GTHR, GEMM_SMEM>>>(hq, hWq, bq, qh,
                                               hk, hWk, bk, kh,
                                               hv, hWv, bv, vh);

    head_attn<<<NTOK / 2, 256>>>(qh, kh, vh, att);

    dim3 gg(DM / BN, NTOK / BM, 1);   // (8, 128)
    gemm_h<float, 1><<<gg, GTHR, GEMM_SMEM>>>(att, hWo, bo, out,
                                              att, hWo, bo, out,
                                              att, hWo, bo, out);
}

// round 17
// speedup vs baseline: 1.0345x; 1.0345x over previous
#include <cuda_runtime.h>
#include <cuda_fp16.h>
#include <cstdint>

#define NTOK 16384
#define DM   1024
#define NH   16
#define HD   64
#define KD   1024

// ---------------- scratch ----------------
__device__ __half g_hq [(size_t)NTOK * DM];
__device__ __half g_hk [(size_t)NTOK * DM];
__device__ __half g_hv [(size_t)NTOK * DM];
__device__ __half g_hWq[(size_t)DM * DM];
__device__ __half g_hWk[(size_t)DM * DM];
__device__ __half g_hWv[(size_t)DM * DM];
__device__ __half g_hWo[(size_t)DM * DM];
__device__ __half g_qh [(size_t)NTOK * DM];
__device__ __half g_kh [(size_t)NTOK * DM];
__device__ __half g_vh [(size_t)NTOK * DM];
__device__ __half g_att[(size_t)NTOK * DM];

__device__ __forceinline__ uint32_t smem_u32(const void* p) {
    uint32_t a;
    asm("{ .reg .u64 t; cvta.to.shared.u64 t, %1; cvt.u32.u64 %0, t; }" : "=r"(a) : "l"(p));
    return a;
}

// ---------------------------------------------------------------------------
// GEMM (frozen — at the legacy-HMMA hardware rate):
// BM=128 BN=128 BK=64, 128 thr, 4 warps (2x2), warp tile 64x64,
// NST=3 cp.async pipeline, 96KB smem, 2 CTAs/SM, frag double-buffering.
// ---------------------------------------------------------------------------
#define BM 128
#define BN 128
#define BK 64
#define NKT (KD / BK)            // 16
#define NST 3
#define ASTG 16384
#define BSTG 16384
#define BOFF (NST * ASTG)
#define GEMM_SMEM (NST * (ASTG + BSTG))   // 98304
#define GTHR 128

#define LDSM_X4(r0, r1, r2, r3, addr)                                           \
    asm volatile("ldmatrix.sync.aligned.m8n8.x4.shared.b16 {%0,%1,%2,%3}, [%4];" \
                 : "=r"(r0), "=r"(r1), "=r"(r2), "=r"(r3) : "r"(addr))

#define MMA_F16(acc, a, b0, b1)                                                 \
    asm volatile("mma.sync.aligned.m16n8k16.row.col.f32.f16.f16.f32 "           \
                 "{%0,%1,%2,%3}, {%4,%5,%6,%7}, {%8,%9}, {%0,%1,%2,%3};\n"      \
                 : "+f"((acc)[0]), "+f"((acc)[1]), "+f"((acc)[2]), "+f"((acc)[3]) \
                 : "r"((a)[0]), "r"((a)[1]), "r"((a)[2]), "r"((a)[3]),          \
                   "r"(b0), "r"(b1))

#define CP_ASYNC16(dst, src) \
    asm volatile("cp.async.cg.shared.global [%0], [%1], 16;" :: "r"(dst), "l"(src))
#define CP_COMMIT() asm volatile("cp.async.commit_group;")
#define CP_WAIT1()  asm volatile("cp.async.wait_group 1;")

template <typename OutT, int NZ>
__global__ __launch_bounds__(GTHR, 2)
void gemm_h(const __half* __restrict__ A0, const __half* __restrict__ W0,
            const float* __restrict__ b0_, OutT* __restrict__ C0,
            const __half* __restrict__ A1, const __half* __restrict__ W1,
            const float* __restrict__ b1_, OutT* __restrict__ C1,
            const __half* __restrict__ A2, const __half* __restrict__ W2,
            const float* __restrict__ b2_, OutT* __restrict__ C2)
{
    const __half* A;   const __half* W;
    const float*  bias; OutT* C;
    if (NZ == 1 || blockIdx.z == 0) { A = A0; W = W0; bias = b0_; C = C0; }
    else if (blockIdx.z == 1)       { A = A1; W = W1; bias = b1_; C = C1; }
    else                            { A = A2; W = W2; bias = b2_; C = C2; }

    extern __shared__ char smem[];
    const uint32_t sb = smem_u32(smem);

    const int t    = threadIdx.x;
    const int warp = t >> 5;
    const int lane = t & 31;
    const int wm   = warp >> 1;
    const int wn   = warp & 1;
    const int m0   = blockIdx.y * BM;
    const int n0   = blockIdx.x * BN;

    auto stage = [&](int kt) {
        const int s = (kt % NST);
        const uint32_t sa = sb + s * ASTG;
        const uint32_t sw = sb + BOFF + s * BSTG;
        #pragma unroll
        for (int i = 0; i < 8; i++) {
            int id  = t + i * GTHR;
            int row = id >> 3, c16 = id & 7;
            const __half* src = A + (size_t)(m0 + row) * KD + kt * BK + c16 * 8;
            CP_ASYNC16(sa + row * 128 + ((c16 ^ (row & 7)) << 4), src);
        }
        #pragma unroll
        for (int i = 0; i < 8; i++) {
            int id  = t + i * GTHR;
            int row = id >> 3, c16 = id & 7;
            const __half* src = W + (size_t)(n0 + row) * KD + kt * BK + c16 * 8;
            CP_ASYNC16(sw + row * 128 + ((c16 ^ (row & 7)) << 4), src);
        }
    };

    float acc[4][8][4];
    #pragma unroll
    for (int mi = 0; mi < 4; mi++)
        #pragma unroll
        for (int ni = 0; ni < 8; ni++)
            #pragma unroll
            for (int r = 0; r < 4; r++) acc[mi][ni][r] = 0.f;

    const int tl   = lane >> 3;
    const int tr   = lane & 7;
    const int rsel = (tl & 1) * 8;
    const int khh  = tl >> 1;

    uint32_t aRow[4], bRow[4];
    #pragma unroll
    for (int mi = 0; mi < 4; mi++) aRow[mi] = (wm * 64 + mi * 16 + rsel + tr) * 128;
    #pragma unroll
    for (int nj = 0; nj < 4; nj++) bRow[nj] = (wn * 64 + nj * 16 + rsel + tr) * 128;

    auto ldfrag = [&](uint32_t aB, uint32_t bB, int ks,
                      uint32_t (*a)[4], uint32_t (*bf)[4]) {
        const uint32_t kcx = (uint32_t)(((ks * 2 + khh) ^ tr) << 4);
        #pragma unroll
        for (int mi = 0; mi < 4; mi++)
            LDSM_X4(a[mi][0], a[mi][1], a[mi][2], a[mi][3], aB + aRow[mi] + kcx);
        #pragma unroll
        for (int nj = 0; nj < 4; nj++)
            LDSM_X4(bf[nj][0], bf[nj][1], bf[nj][2], bf[nj][3], bB + bRow[nj] + kcx);
    };

    auto compute = [&](int s) {
        const uint32_t aB = sb + s * ASTG;
        const uint32_t bB = sb + BOFF + s * BSTG;
        uint32_t a[2][4][4], bf[2][4][4];
        ldfrag(aB, bB, 0, a[0], bf[0]);
        #pragma unroll
        for (int ks = 0; ks < 4; ks++) {
            const int cur = ks & 1;
            if (ks < 3) ldfrag(aB, bB, ks + 1, a[cur ^ 1], bf[cur ^ 1]);
            #pragma unroll
            for (int mi = 0; mi < 4; mi++)
                #pragma unroll
                for (int n8 = 0; n8 < 8; n8++) {
                    const int nj = n8 >> 1, hi = n8 & 1;
                    MMA_F16(acc[mi][n8], a[cur][mi], bf[cur][nj][hi], bf[cur][nj][hi + 2]);
                }
        }
    };

    stage(0); CP_COMMIT();
    stage(1); CP_COMMIT();

    for (int kt = 0; kt < NKT; kt++) {
        CP_WAIT1();
        __syncthreads();
        if (kt + 2 < NKT) stage(kt + 2);
        CP_COMMIT();
        compute(kt % NST);
    }

    const int gq = lane >> 2, tg = lane & 3;
    #pragma unroll
    for (int mi = 0; mi < 4; mi++) {
        const int r = m0 + wm * 64 + mi * 16 + gq;
        #pragma unroll
        for (int ni = 0; ni < 8; ni++) {
            const int cc = n0 + wn * 64 + ni * 8 + tg * 2;
            const float bb0 = __ldg(bias + cc);
            const float bb1 = __ldg(bias + cc + 1);
            if constexpr (sizeof(OutT) == 2) {
                *(__half2*)((__half*)C + (size_t)r * DM + cc) =
                    __floats2half2_rn(acc[mi][ni][0] + bb0, acc[mi][ni][1] + bb1);
                *(__half2*)((__half*)C + (size_t)(r + 8) * DM + cc) =
                    __floats2half2_rn(acc[mi][ni][2] + bb0, acc[mi][ni][3] + bb1);
            } else {
                *(float2*)((float*)C + (size_t)r * DM + cc) =
                    make_float2(acc[mi][ni][0] + bb0, acc[mi][ni][1] + bb1);
                *(float2*)((float*)C + (size_t)(r + 8) * DM + cc) =
                    make_float2(acc[mi][ni][2] + bb0, acc[mi][ni][3] + bb1);
            }
        }
    }
}

// ---------------- fused fp32 -> fp16 conversion (single launch) -------------
__global__ __launch_bounds__(256)
void cvt_all(const float4* __restrict__ q,  uint2* __restrict__ hq,
             const float4* __restrict__ k,  uint2* __restrict__ hk,
             const float4* __restrict__ v,  uint2* __restrict__ hv,
             const float4* __restrict__ w0, uint2* __restrict__ hw0,
             const float4* __restrict__ w1, uint2* __restrict__ hw1,
             const float4* __restrict__ w2, uint2* __restrict__ hw2,
             const float4* __restrict__ w3, uint2* __restrict__ hw3)
{
    const int b = blockIdx.x;
    const float4* in;
    uint2* out;
    int lb;
    if (b < 12288) {
        int ts = b >> 12;
        lb = b & 4095;
        in  = (ts == 0) ? q  : (ts == 1) ? k  : v;
        out = (ts == 0) ? hq : (ts == 1) ? hk : hv;
    } else {
        int w = b - 12288;
        int ts = w >> 8;
        lb = w & 255;
        in  = (ts == 0) ? w0  : (ts == 1) ? w1  : (ts == 2) ? w2  : w3;
        out = (ts == 0) ? hw0 : (ts == 1) ? hw1 : (ts == 2) ? hw2 : hw3;
    }
    int base = lb * 1024 + threadIdx.x;
    float4 vv[4];
    #pragma unroll
    for (int j = 0; j < 4; j++) vv[j] = in[base + j * 256];
    #pragma unroll
    for (int j = 0; j < 4; j++) {
        __half2 h0 = __floats2half2_rn(vv[j].x, vv[j].y);
        __half2 h1 = __floats2half2_rn(vv[j].z, vv[j].w);
        out[base + j * 256] = make_uint2(*(uint32_t*)&h0, *(uint32_t*)&h1);
    }
}

// ---------------- per-token head-mixing attention (R12 best variant) --------
#define QROW 9    // uint4 per smem row (8 data + 1 pad)

__global__ __launch_bounds__(256)
void head_attn(const __half* __restrict__ qh, const __half* __restrict__ kh,
               const __half* __restrict__ vh, __half* __restrict__ out)
{
    __shared__ uint4 qsh[2][NH * QROW];
    __shared__ uint4 ksh[2][NH * QROW];
    __shared__ uint4 vsh[2][NH * QROW];
    __shared__ float sc[2][NH][NH + 1];

    const int tok0 = blockIdx.x * 2;
    const int t    = threadIdx.x;

    {
        int row = t >> 3;
        int ti  = row >> 4;
        int r   = row & 15;
        int c   = t & 7;
        const size_t base = (size_t)(tok0 + ti) * DM + r * HD;
        qsh[ti][r * QROW + c] = *((const uint4*)(qh + base) + c);
        ksh[ti][r * QROW + c] = *((const uint4*)(kh + base) + c);
        vsh[ti][r * QROW + c] = *((const uint4*)(vh + base) + c);
    }
    __syncthreads();

    {
        const int h = t >> 4, g = t & 15;
        #pragma unroll
        for (int ti = 0; ti < 2; ti++) {
            const uint4* qr = &qsh[ti][h * QROW];
            const uint4* kr = &ksh[ti][g * QROW];
            uint4 qa = qr[0], ka = kr[0];
            __half2 a0 = __hmul2(*(__half2*)&qa.x, *(__half2*)&ka.x);
            __half2 a1 = __hmul2(*(__half2*)&qa.y, *(__half2*)&ka.y);
            __half2 a2 = __hmul2(*(__half2*)&qa.z, *(__half2*)&ka.z);
            __half2 a3 = __hmul2(*(__half2*)&qa.w, *(__half2*)&ka.w);
            #pragma unroll
            for (int c = 1; c < 8; c++) {
                qa = qr[c]; ka = kr[c];
                a0 = __hfma2(*(__half2*)&qa.x, *(__half2*)&ka.x, a0);
                a1 = __hfma2(*(__half2*)&qa.y, *(__half2*)&ka.y, a1);
                a2 = __hfma2(*(__half2*)&qa.z, *(__half2*)&ka.z, a2);
                a3 = __hfma2(*(__half2*)&qa.w, *(__half2*)&ka.w, a3);
            }
            float2 f0 = __half22float2(a0);
            float2 f1 = __half22float2(a1);
            float2 f2 = __half22float2(a2);
            float2 f3 = __half22float2(a3);
            float s = (f0.x + f0.y) + (f1.x + f1.y)
                    + (f2.x + f2.y) + (f3.x + f3.y);
            sc[ti][h][g] = s * 0.125f;
        }
    }
    __syncthreads();

    if (t < 32) {
        int ti = t >> 4, r = t & 15;
        float m = sc[ti][r][0];
        #pragma unroll
        for (int g = 1; g < NH; g++) m = fmaxf(m, sc[ti][r][g]);
        float e[NH], sum = 0.f;
        #pragma unroll
        for (int g = 0; g < NH; g++) { e[g] = __expf(sc[ti][r][g] - m); sum += e[g]; }
        float inv = 1.f / sum;
        #pragma unroll
        for (int g = 0; g < NH; g++) sc[ti][r][g] = e[g] * inv;
    }
    __syncthreads();

    {
        const int h  = t >> 4;
        const int c2 = t & 15;
        #pragma unroll
        for (int ti = 0; ti < 2; ti++) {
            float4 acc = make_float4(0.f, 0.f, 0.f, 0.f);
            const char* vbase = (const char*)&vsh[ti][0];
            #pragma unroll
            for (int g = 0; g < NH; g++) {
                float w = sc[ti][h][g];
                uint2 va = *(const uint2*)(vbase + (size_t)g * QROW * 16 + c2 * 8);
                float2 v0 = __half22float2(*(__half2*)&va.x);
                float2 v1 = __half22float2(*(__half2*)&va.y);
                acc.x += w * v0.x; acc.y += w * v0.y;
                acc.z += w * v1.x; acc.w += w * v1.y;
            }
            __half2 h0 = __floats2half2_rn(acc.x, acc.y);
            __half2 h1 = __floats2half2_rn(acc.z, acc.w);
            *(uint2*)(out + (size_t)(tok0 + ti) * DM + h * HD + c2 * 4) =
                make_uint2(*(uint32_t*)&h0, *(uint32_t*)&h1);
        }
    }
}

// ---------------------------------------------------------------------------
extern "C" void kernel_launch(void* const* d_in, const int* in_sizes, int n_in,
                              void* d_out, int out_size)
{
    const float* q  = (const float*)d_in[0];
    const float* k  = (const float*)d_in[1];
    const float* v  = (const float*)d_in[2];
    const float* Wq = (const float*)d_in[3];
    const float* bq = (const float*)d_in[4];
    const float* Wk = (const float*)d_in[5];
    const float* bk = (const float*)d_in[6];
    const float* Wv = (const float*)d_in[7];
    const float* bv = (const float*)d_in[8];
    const float* Wo = (const float*)d_in[9];
    const float* bo = (const float*)d_in[10];
    float* out = (float*)d_out;

    __half *hq, *hk, *hv, *hWq, *hWk, *hWv, *hWo, *qh, *kh, *vh, *att;
    cudaGetSymbolAddress((void**)&hq,  g_hq);
    cudaGetSymbolAddress((void**)&hk,  g_hk);
    cudaGetSymbolAddress((void**)&hv,  g_hv);
    cudaGetSymbolAddress((void**)&hWq, g_hWq);
    cudaGetSymbolAddress((void**)&hWk, g_hWk);
    cudaGetSymbolAddress((void**)&hWv, g_hWv);
    cudaGetSymbolAddress((void**)&hWo, g_hWo);
    cudaGetSymbolAddress((void**)&qh,  g_qh);
    cudaGetSymbolAddress((void**)&kh,  g_kh);
    cudaGetSymbolAddress((void**)&vh,  g_vh);
    cudaGetSymbolAddress((void**)&att, g_att);

    cudaFuncSetAttribute((const void*)gemm_h<__half, 3>,
                         cudaFuncAttributeMaxDynamicSharedMemorySize, GEMM_SMEM);
    cudaFuncSetAttribute((const void*)gemm_h<float, 1>,
                         cudaFuncAttributeMaxDynamicSharedMemorySize, GEMM_SMEM);

    cvt_all<<<13312, 256>>>((const float4*)q,  (uint2*)hq,
                            (const float4*)k,  (uint2*)hk,
                            (const float4*)v,  (uint2*)hv,
                            (const float4*)Wq, (uint2*)hWq,
                            (const float4*)Wk, (uint2*)hWk,
                            (const float4*)Wv, (uint2*)hWv,
                            (const float4*)Wo, (uint2*)hWo);

    dim3 gp(DM / BN, NTOK / BM, 3);   // (8, 128, 3)
    gemm_h<__half, 3><<<gp, GTHR, GEMM_SMEM>>>(hq, hWq, bq, qh,
                                               hk, hWk, bk, kh,
                                               hv, hWv, bv, vh);

    head_attn<<<NTOK / 2, 256>>>(qh, kh, vh, att);

    dim3 gg(DM / BN, NTOK / BM, 1);   // (8, 128)
    gemm_h<float, 1><<<gg, GTHR, GEMM_SMEM>>>(att, hWo, bo, out,
                                              att, hWo, bo, out,
                                              att, hWo, bo, out);
}